// round 1
// baseline (speedup 1.0000x reference)
#include <cuda_runtime.h>

#define EMBED 1024
#define NHEAD 16
#define HD 64
#define BATCH 2
#define SEQ 2048
#define ROWS (BATCH * SEQ)   // 4096

// Scratch for projected Q/K/V in [B][H][S][Hd] layout (16 MB each).
__device__ float g_q[(size_t)BATCH * NHEAD * SEQ * HD];
__device__ float g_k[(size_t)BATCH * NHEAD * SEQ * HD];
__device__ float g_v[(size_t)BATCH * NHEAD * SEQ * HD];

// ---------------------------------------------------------------------------
// QKV projection: out = x @ W + b, written as [B][H][S][Hd].
// 64x64 tile per block, 256 threads, 4x4 per thread, K-chunk 16.
// blockIdx.z in {0,1,2} selects (Wq,bq,g_q), (Wk,bk,g_k), (Wv,bv,g_v).
// ---------------------------------------------------------------------------
__global__ __launch_bounds__(256) void qkv_kernel(
    const float* __restrict__ x,
    const float* __restrict__ Wq, const float* __restrict__ bq,
    const float* __restrict__ Wk, const float* __restrict__ bk,
    const float* __restrict__ Wv, const float* __restrict__ bv)
{
    __shared__ float As[16][64];   // [k][m] (transposed store)
    __shared__ float Bs[16][64];   // [k][n]

    const float* W;
    const float* bias;
    float* out;
    if (blockIdx.z == 0)      { W = Wq; bias = bq; out = g_q; }
    else if (blockIdx.z == 1) { W = Wk; bias = bk; out = g_k; }
    else                      { W = Wv; bias = bv; out = g_v; }

    const int t  = threadIdx.x;
    const int tx = t & 15;          // n sub-tile
    const int ty = t >> 4;          // m sub-tile
    const int m0 = blockIdx.y * 64;
    const int n0 = blockIdx.x * 64;

    // loader mapping
    const int lar = t >> 2;          // A row 0..63
    const int lac = (t & 3) * 4;     // A k-offset {0,4,8,12}
    const int lbk = t >> 4;          // B k 0..15
    const int lbc = (t & 15) * 4;    // B col

    float acc[4][4] = {};

    for (int k0 = 0; k0 < EMBED; k0 += 16) {
        float4 av = *(const float4*)&x[(size_t)(m0 + lar) * EMBED + k0 + lac];
        float4 bv4 = *(const float4*)&W[(size_t)(k0 + lbk) * EMBED + n0 + lbc];
        As[lac + 0][lar] = av.x;
        As[lac + 1][lar] = av.y;
        As[lac + 2][lar] = av.z;
        As[lac + 3][lar] = av.w;
        *(float4*)&Bs[lbk][lbc] = bv4;
        __syncthreads();

#pragma unroll
        for (int k = 0; k < 16; k++) {
            float4 a4 = *(const float4*)&As[k][ty * 4];
            float4 b4 = *(const float4*)&Bs[k][tx * 4];
            float ar[4] = {a4.x, a4.y, a4.z, a4.w};
            float br[4] = {b4.x, b4.y, b4.z, b4.w};
#pragma unroll
            for (int i = 0; i < 4; i++)
#pragma unroll
                for (int j = 0; j < 4; j++)
                    acc[i][j] += ar[i] * br[j];
        }
        __syncthreads();
    }

    // epilogue: add bias, scatter into [B][H][S][Hd]
    const int h = n0 >> 6;  // head index (HD == 64 == tile N)
    float bvec[4];
#pragma unroll
    for (int j = 0; j < 4; j++) bvec[j] = bias[n0 + tx * 4 + j];

#pragma unroll
    for (int i = 0; i < 4; i++) {
        int m = m0 + ty * 4 + i;
        int b = m >> 11;          // / SEQ
        int s = m & (SEQ - 1);
        float4 o;
        o.x = acc[i][0] + bvec[0];
        o.y = acc[i][1] + bvec[1];
        o.z = acc[i][2] + bvec[2];
        o.w = acc[i][3] + bvec[3];
        size_t idx = (((size_t)b * NHEAD + h) * SEQ + s) * HD + tx * 4;
        *(float4*)&out[idx] = o;
    }
}

// ---------------------------------------------------------------------------
// Flash attention: per block 64 queries x full head, online softmax.
// NOTE: reference applies NO 1/sqrt(head_dim) scaling.
// smem: QsT[64d][68], KsT[64d][68], Vs[64c][64], Ps[64r][64]  = 66 KB
// ---------------------------------------------------------------------------
#define TSTR 68
#define ATTN_SMEM ((64 * TSTR * 2 + 64 * 64 * 2) * 4)

__global__ __launch_bounds__(256) void attn_kernel(float* __restrict__ out)
{
    extern __shared__ float sm[];
    float* Qs = sm;                   // [d][r], stride TSTR
    float* Ks = Qs + 64 * TSTR;       // [d][c], stride TSTR
    float* Vs = Ks + 64 * TSTR;       // [c][d], stride 64
    float* Ps = Vs + 64 * 64;         // [r][c], stride 64

    const int bh = blockIdx.y;                 // b*NHEAD + h
    const int q0 = blockIdx.x * 64;
    const float* Qg = g_q + (size_t)bh * SEQ * HD;
    const float* Kg = g_k + (size_t)bh * SEQ * HD;
    const float* Vg = g_v + (size_t)bh * SEQ * HD;

    const int t  = threadIdx.x;
    const int tx = t & 15;
    const int ty = t >> 4;

    // Load Q tile transposed into Qs[d][r]
#pragma unroll
    for (int p = 0; p < 4; p++) {
        int f  = p * 256 + t;          // float4 id 0..1023
        int r  = f >> 4;               // 0..63
        int d4 = (f & 15) * 4;
        float4 v = *(const float4*)&Qg[(size_t)(q0 + r) * HD + d4];
        Qs[(d4 + 0) * TSTR + r] = v.x;
        Qs[(d4 + 1) * TSTR + r] = v.y;
        Qs[(d4 + 2) * TSTR + r] = v.z;
        Qs[(d4 + 3) * TSTR + r] = v.w;
    }

    float m_i[4], l_i[4], o[4][4];
#pragma unroll
    for (int i = 0; i < 4; i++) {
        m_i[i] = -1e30f;
        l_i[i] = 0.f;
#pragma unroll
        for (int j = 0; j < 4; j++) o[i][j] = 0.f;
    }

    for (int kt = 0; kt < SEQ; kt += 64) {
        __syncthreads();   // previous iteration's PV reads done before refill

        // Load K tile transposed and V tile straight
#pragma unroll
        for (int p = 0; p < 4; p++) {
            int f  = p * 256 + t;
            int r  = f >> 4;
            int d4 = (f & 15) * 4;
            float4 kv = *(const float4*)&Kg[(size_t)(kt + r) * HD + d4];
            Ks[(d4 + 0) * TSTR + r] = kv.x;
            Ks[(d4 + 1) * TSTR + r] = kv.y;
            Ks[(d4 + 2) * TSTR + r] = kv.z;
            Ks[(d4 + 3) * TSTR + r] = kv.w;
            float4 vv = *(const float4*)&Vg[(size_t)(kt + r) * HD + d4];
            *(float4*)&Vs[r * 64 + d4] = vv;
        }
        __syncthreads();

        // S = Q K^T  (4x4 per thread)
        float s_[4][4] = {};
#pragma unroll 16
        for (int d = 0; d < 64; d++) {
            float4 q4 = *(const float4*)&Qs[d * TSTR + ty * 4];
            float4 k4 = *(const float4*)&Ks[d * TSTR + tx * 4];
            float qr[4] = {q4.x, q4.y, q4.z, q4.w};
            float kr[4] = {k4.x, k4.y, k4.z, k4.w};
#pragma unroll
            for (int i = 0; i < 4; i++)
#pragma unroll
                for (int j = 0; j < 4; j++)
                    s_[i][j] += qr[i] * kr[j];
        }

        // online softmax per row (16 lanes per row-group share via shfl)
#pragma unroll
        for (int i = 0; i < 4; i++) {
            float lm = fmaxf(fmaxf(s_[i][0], s_[i][1]), fmaxf(s_[i][2], s_[i][3]));
#pragma unroll
            for (int msk = 1; msk < 16; msk <<= 1)
                lm = fmaxf(lm, __shfl_xor_sync(0xffffffffu, lm, msk));
            float mn = fmaxf(m_i[i], lm);
            float corr = __expf(m_i[i] - mn);
            m_i[i] = mn;
            float rs = 0.f;
#pragma unroll
            for (int j = 0; j < 4; j++) {
                float p = __expf(s_[i][j] - mn);
                s_[i][j] = p;
                rs += p;
            }
#pragma unroll
            for (int msk = 1; msk < 16; msk <<= 1)
                rs += __shfl_xor_sync(0xffffffffu, rs, msk);
            l_i[i] = l_i[i] * corr + rs;
#pragma unroll
            for (int j = 0; j < 4; j++) o[i][j] *= corr;
            float4 pv = make_float4(s_[i][0], s_[i][1], s_[i][2], s_[i][3]);
            *(float4*)&Ps[(ty * 4 + i) * 64 + tx * 4] = pv;
        }
        __syncthreads();

        // O += P V  (thread: rows ty*4.., dims tx*4..)
#pragma unroll 8
        for (int c = 0; c < 64; c++) {
            float4 v4 = *(const float4*)&Vs[c * 64 + tx * 4];
#pragma unroll
            for (int i = 0; i < 4; i++) {
                float p = Ps[(ty * 4 + i) * 64 + c];
                o[i][0] += p * v4.x;
                o[i][1] += p * v4.y;
                o[i][2] += p * v4.z;
                o[i][3] += p * v4.w;
            }
        }
    }

    // normalize and write [B][S][D]
    const int b = bh >> 4;
    const int h = bh & 15;
#pragma unroll
    for (int i = 0; i < 4; i++) {
        float inv = 1.0f / l_i[i];
        float4 ov = make_float4(o[i][0] * inv, o[i][1] * inv,
                                o[i][2] * inv, o[i][3] * inv);
        int srow = q0 + ty * 4 + i;
        size_t idx = ((size_t)b * SEQ + srow) * EMBED + h * HD + tx * 4;
        *(float4*)&out[idx] = ov;
    }
}

// ---------------------------------------------------------------------------
extern "C" void kernel_launch(void* const* d_in, const int* in_sizes, int n_in,
                              void* d_out, int out_size)
{
    const float* x  = (const float*)d_in[0];
    const float* Wq = (const float*)d_in[1];
    const float* bq = (const float*)d_in[2];
    const float* Wk = (const float*)d_in[3];
    const float* bk = (const float*)d_in[4];
    const float* Wv = (const float*)d_in[5];
    const float* bv = (const float*)d_in[6];
    float* out = (float*)d_out;

    dim3 g1(EMBED / 64, ROWS / 64, 3);
    qkv_kernel<<<g1, 256>>>(x, Wq, bq, Wk, bk, Wv, bv);

    cudaFuncSetAttribute(attn_kernel,
                         cudaFuncAttributeMaxDynamicSharedMemorySize, ATTN_SMEM);
    dim3 g2(SEQ / 64, BATCH * NHEAD);
    attn_kernel<<<g2, 256, ATTN_SMEM>>>(out);
}

// round 2
// speedup vs baseline: 1.1266x; 1.1266x over previous
#include <cuda_runtime.h>

#define EMBED 1024
#define NHEAD 16
#define HD 64
#define BATCH 2
#define SEQ 2048
#define ROWS (BATCH * SEQ)   // 4096

// Scratch for projected Q/K/V in [B][H][S][Hd] layout (16 MB each).
__device__ float g_q[(size_t)BATCH * NHEAD * SEQ * HD];
__device__ float g_k[(size_t)BATCH * NHEAD * SEQ * HD];
__device__ float g_v[(size_t)BATCH * NHEAD * SEQ * HD];

// ---------------------------------------------------------------------------
// QKV projection: out = x @ W + b, written as [B][H][S][Hd].
// 128x128 tile per block, 256 threads, 8x8 per thread, K-chunk 16.
// blockIdx.z in {0,1,2} selects (Wq,bq,g_q), (Wk,bk,g_k), (Wv,bv,g_v).
// ---------------------------------------------------------------------------
__global__ __launch_bounds__(256) void qkv_kernel(
    const float* __restrict__ x,
    const float* __restrict__ Wq, const float* __restrict__ bq,
    const float* __restrict__ Wk, const float* __restrict__ bk,
    const float* __restrict__ Wv, const float* __restrict__ bv)
{
    __shared__ float As[16][132];   // [k][m] (transposed store)
    __shared__ float Bs[16][132];   // [k][n]

    const float* W;
    const float* bias;
    float* out;
    if (blockIdx.z == 0)      { W = Wq; bias = bq; out = g_q; }
    else if (blockIdx.z == 1) { W = Wk; bias = bk; out = g_k; }
    else                      { W = Wv; bias = bv; out = g_v; }

    const int t  = threadIdx.x;
    const int tx = t & 15;          // n sub-tile (8 cols)
    const int ty = t >> 4;          // m sub-tile (8 rows)
    const int m0 = blockIdx.y * 128;
    const int n0 = blockIdx.x * 128;

    float acc[8][8] = {};

    for (int k0 = 0; k0 < EMBED; k0 += 16) {
#pragma unroll
        for (int p = 0; p < 2; p++) {
            int f  = p * 256 + t;
            // A: 128 rows x 16 k, transposed into As[k][m]
            int ar = f >> 2;            // 0..127
            int ak = (f & 3) * 4;       // 0,4,8,12
            float4 av = *(const float4*)&x[(size_t)(m0 + ar) * EMBED + k0 + ak];
            As[ak + 0][ar] = av.x;
            As[ak + 1][ar] = av.y;
            As[ak + 2][ar] = av.z;
            As[ak + 3][ar] = av.w;
            // B: 16 k x 128 cols
            int bk_ = f >> 5;           // 0..15
            int bc  = (f & 31) * 4;     // 0..124
            *(float4*)&Bs[bk_][bc] =
                *(const float4*)&W[(size_t)(k0 + bk_) * EMBED + n0 + bc];
        }
        __syncthreads();

#pragma unroll
        for (int k = 0; k < 16; k++) {
            float4 a0 = *(const float4*)&As[k][ty * 8];
            float4 a1 = *(const float4*)&As[k][ty * 8 + 4];
            float4 b0 = *(const float4*)&Bs[k][tx * 8];
            float4 b1 = *(const float4*)&Bs[k][tx * 8 + 4];
            float ar[8] = {a0.x, a0.y, a0.z, a0.w, a1.x, a1.y, a1.z, a1.w};
            float br[8] = {b0.x, b0.y, b0.z, b0.w, b1.x, b1.y, b1.z, b1.w};
#pragma unroll
            for (int i = 0; i < 8; i++)
#pragma unroll
                for (int j = 0; j < 8; j++)
                    acc[i][j] += ar[i] * br[j];
        }
        __syncthreads();
    }

    // epilogue: add bias, scatter into [B][H][S][Hd]
    float bvec[8];
#pragma unroll
    for (int j = 0; j < 8; j++) bvec[j] = bias[n0 + tx * 8 + j];
    const int col0 = n0 + tx * 8;
    const int h    = col0 >> 6;        // 8-col group never crosses a head
    const int hc   = col0 & 63;

#pragma unroll
    for (int i = 0; i < 8; i++) {
        int m = m0 + ty * 8 + i;
        int b = m >> 11;               // / SEQ
        int s = m & (SEQ - 1);
        size_t base = (((size_t)b * NHEAD + h) * SEQ + s) * HD + hc;
        float4 o0, o1;
        o0.x = acc[i][0] + bvec[0];
        o0.y = acc[i][1] + bvec[1];
        o0.z = acc[i][2] + bvec[2];
        o0.w = acc[i][3] + bvec[3];
        o1.x = acc[i][4] + bvec[4];
        o1.y = acc[i][5] + bvec[5];
        o1.z = acc[i][6] + bvec[6];
        o1.w = acc[i][7] + bvec[7];
        *(float4*)&out[base]     = o0;
        *(float4*)&out[base + 4] = o1;
    }
}

// ---------------------------------------------------------------------------
// Flash attention: BQ=128 queries x BK=128 keys per tile, online softmax.
// NOTE: reference applies NO 1/sqrt(head_dim) scaling.
// 256 threads. S stage: 8x8 per thread. PV stage: 8 rows x 4 dims per thread,
// P read as contiguous float4 over the key dimension.
// smem: QsT[64][132], KsT[64][132], Vs[128][64], Ps[128][132]  ~164 KB
// ---------------------------------------------------------------------------
#define QST 132
#define PST 132
#define ATTN_SMEM ((64 * QST * 2 + 128 * 64 + 128 * PST) * 4)

__global__ __launch_bounds__(256) void attn_kernel(float* __restrict__ out)
{
    extern __shared__ float sm[];
    float* Qs = sm;                   // [d][r], stride QST
    float* Ks = Qs + 64 * QST;        // [d][c], stride QST
    float* Vs = Ks + 64 * QST;        // [c][d], stride 64
    float* Ps = Vs + 128 * 64;        // [r][c], stride PST

    const int bh = blockIdx.y;                 // b*NHEAD + h
    const int q0 = blockIdx.x * 128;
    const float* Qg = g_q + (size_t)bh * SEQ * HD;
    const float* Kg = g_k + (size_t)bh * SEQ * HD;
    const float* Vg = g_v + (size_t)bh * SEQ * HD;

    const int t  = threadIdx.x;
    const int tx = t & 15;
    const int ty = t >> 4;

    // Load Q tile (128 rows x 64 d) transposed into Qs[d][r]
#pragma unroll
    for (int p = 0; p < 8; p++) {
        int f  = p * 256 + t;          // float4 id 0..2047
        int r  = f >> 4;               // 0..127
        int d4 = (f & 15) * 4;
        float4 v = *(const float4*)&Qg[(size_t)(q0 + r) * HD + d4];
        Qs[(d4 + 0) * QST + r] = v.x;
        Qs[(d4 + 1) * QST + r] = v.y;
        Qs[(d4 + 2) * QST + r] = v.z;
        Qs[(d4 + 3) * QST + r] = v.w;
    }

    float m_i[8], l_i[8], o[8][4];
#pragma unroll
    for (int i = 0; i < 8; i++) {
        m_i[i] = -1e30f;
        l_i[i] = 0.f;
#pragma unroll
        for (int j = 0; j < 4; j++) o[i][j] = 0.f;
    }

    for (int kt = 0; kt < SEQ; kt += 128) {
        __syncthreads();   // previous iteration's PV reads done before refill

        // Load K tile transposed and V tile straight
#pragma unroll
        for (int p = 0; p < 8; p++) {
            int f  = p * 256 + t;
            int r  = f >> 4;
            int d4 = (f & 15) * 4;
            float4 kv = *(const float4*)&Kg[(size_t)(kt + r) * HD + d4];
            Ks[(d4 + 0) * QST + r] = kv.x;
            Ks[(d4 + 1) * QST + r] = kv.y;
            Ks[(d4 + 2) * QST + r] = kv.z;
            Ks[(d4 + 3) * QST + r] = kv.w;
            float4 vv = *(const float4*)&Vg[(size_t)(kt + r) * HD + d4];
            *(float4*)&Vs[r * 64 + d4] = vv;
        }
        __syncthreads();

        // S = Q K^T  (8x8 per thread)
        float s_[8][8] = {};
#pragma unroll 8
        for (int d = 0; d < 64; d++) {
            float4 q0v = *(const float4*)&Qs[d * QST + ty * 8];
            float4 q1v = *(const float4*)&Qs[d * QST + ty * 8 + 4];
            float4 k0v = *(const float4*)&Ks[d * QST + tx * 8];
            float4 k1v = *(const float4*)&Ks[d * QST + tx * 8 + 4];
            float qr[8] = {q0v.x, q0v.y, q0v.z, q0v.w, q1v.x, q1v.y, q1v.z, q1v.w};
            float kr[8] = {k0v.x, k0v.y, k0v.z, k0v.w, k1v.x, k1v.y, k1v.z, k1v.w};
#pragma unroll
            for (int i = 0; i < 8; i++)
#pragma unroll
                for (int j = 0; j < 8; j++)
                    s_[i][j] += qr[i] * kr[j];
        }

        // online softmax per row (16 lanes per row-group share via shfl)
#pragma unroll
        for (int i = 0; i < 8; i++) {
            float lm = s_[i][0];
#pragma unroll
            for (int j = 1; j < 8; j++) lm = fmaxf(lm, s_[i][j]);
#pragma unroll
            for (int msk = 1; msk < 16; msk <<= 1)
                lm = fmaxf(lm, __shfl_xor_sync(0xffffffffu, lm, msk));
            float mn = fmaxf(m_i[i], lm);
            float corr = __expf(m_i[i] - mn);
            m_i[i] = mn;
            float rs = 0.f;
#pragma unroll
            for (int j = 0; j < 8; j++) {
                float p = __expf(s_[i][j] - mn);
                s_[i][j] = p;
                rs += p;
            }
#pragma unroll
            for (int msk = 1; msk < 16; msk <<= 1)
                rs += __shfl_xor_sync(0xffffffffu, rs, msk);
            l_i[i] = l_i[i] * corr + rs;
#pragma unroll
            for (int j = 0; j < 4; j++) o[i][j] *= corr;
            float4 p0 = make_float4(s_[i][0], s_[i][1], s_[i][2], s_[i][3]);
            float4 p1 = make_float4(s_[i][4], s_[i][5], s_[i][6], s_[i][7]);
            *(float4*)&Ps[(ty * 8 + i) * PST + tx * 8]     = p0;
            *(float4*)&Ps[(ty * 8 + i) * PST + tx * 8 + 4] = p1;
        }
        __syncthreads();

        // O += P V  (thread: rows ty*8.., dims tx*4..; P read float4 over c)
#pragma unroll 4
        for (int c = 0; c < 128; c += 4) {
            float4 v0 = *(const float4*)&Vs[(c + 0) * 64 + tx * 4];
            float4 v1 = *(const float4*)&Vs[(c + 1) * 64 + tx * 4];
            float4 v2 = *(const float4*)&Vs[(c + 2) * 64 + tx * 4];
            float4 v3 = *(const float4*)&Vs[(c + 3) * 64 + tx * 4];
#pragma unroll
            for (int i = 0; i < 8; i++) {
                float4 p4 = *(const float4*)&Ps[(ty * 8 + i) * PST + c];
                o[i][0] += p4.x * v0.x; o[i][1] += p4.x * v0.y;
                o[i][2] += p4.x * v0.z; o[i][3] += p4.x * v0.w;
                o[i][0] += p4.y * v1.x; o[i][1] += p4.y * v1.y;
                o[i][2] += p4.y * v1.z; o[i][3] += p4.y * v1.w;
                o[i][0] += p4.z * v2.x; o[i][1] += p4.z * v2.y;
                o[i][2] += p4.z * v2.z; o[i][3] += p4.z * v2.w;
                o[i][0] += p4.w * v3.x; o[i][1] += p4.w * v3.y;
                o[i][2] += p4.w * v3.z; o[i][3] += p4.w * v3.w;
            }
        }
    }

    // normalize and write [B][S][D]
    const int b = bh >> 4;
    const int h = bh & 15;
#pragma unroll
    for (int i = 0; i < 8; i++) {
        float inv = 1.0f / l_i[i];
        float4 ov = make_float4(o[i][0] * inv, o[i][1] * inv,
                                o[i][2] * inv, o[i][3] * inv);
        int srow = q0 + ty * 8 + i;
        size_t idx = ((size_t)b * SEQ + srow) * EMBED + h * HD + tx * 4;
        *(float4*)&out[idx] = ov;
    }
}

// ---------------------------------------------------------------------------
extern "C" void kernel_launch(void* const* d_in, const int* in_sizes, int n_in,
                              void* d_out, int out_size)
{
    const float* x  = (const float*)d_in[0];
    const float* Wq = (const float*)d_in[1];
    const float* bq = (const float*)d_in[2];
    const float* Wk = (const float*)d_in[3];
    const float* bk = (const float*)d_in[4];
    const float* Wv = (const float*)d_in[5];
    const float* bv = (const float*)d_in[6];
    float* out = (float*)d_out;

    dim3 g1(EMBED / 128, ROWS / 128, 3);
    qkv_kernel<<<g1, 256>>>(x, Wq, bq, Wk, bk, Wv, bv);

    cudaFuncSetAttribute(attn_kernel,
                         cudaFuncAttributeMaxDynamicSharedMemorySize, ATTN_SMEM);
    dim3 g2(SEQ / 128, BATCH * NHEAD);
    attn_kernel<<<g2, 256, ATTN_SMEM>>>(out);
}

// round 4
// speedup vs baseline: 2.7221x; 2.4161x over previous
#include <cuda_runtime.h>
#include <cuda_bf16.h>
#include <cstdint>

#define EMBED 1024
#define NHEAD 16
#define HD 64
#define BATCH 2
#define SEQ 2048
#define ROWS (BATCH * SEQ)   // 4096

// bf16 hi/lo split of x [4096][1024] and of W^T [3][1024(n)][1024(k)].
__device__ __nv_bfloat16 g_xhi[(size_t)ROWS * EMBED];
__device__ __nv_bfloat16 g_xlo[(size_t)ROWS * EMBED];
__device__ __nv_bfloat16 g_whi[(size_t)3 * EMBED * EMBED];
__device__ __nv_bfloat16 g_wlo[(size_t)3 * EMBED * EMBED];

// bf16 hi/lo Q/K/V in [B*H][S][64] layout.
__device__ __nv_bfloat16 g_qhi[(size_t)ROWS * NHEAD * HD];
__device__ __nv_bfloat16 g_qlo[(size_t)ROWS * NHEAD * HD];
__device__ __nv_bfloat16 g_khi[(size_t)ROWS * NHEAD * HD];
__device__ __nv_bfloat16 g_klo[(size_t)ROWS * NHEAD * HD];
__device__ __nv_bfloat16 g_vhi[(size_t)ROWS * NHEAD * HD];
__device__ __nv_bfloat16 g_vlo[(size_t)ROWS * NHEAD * HD];

// ---------------------------------------------------------------------------
// helpers
// ---------------------------------------------------------------------------
__device__ __forceinline__ uint32_t smem_u32(const void* p) {
    uint32_t a;
    asm("{ .reg .u64 t; cvta.to.shared.u64 t, %1; cvt.u32.u64 %0, t; }"
        : "=r"(a) : "l"(p));
    return a;
}
__device__ __forceinline__ void mma16816(float* c, const uint32_t* a,
                                         const uint32_t* b) {
    asm volatile(
        "mma.sync.aligned.m16n8k16.row.col.f32.bf16.bf16.f32 "
        "{%0,%1,%2,%3}, {%4,%5,%6,%7}, {%8,%9}, {%0,%1,%2,%3};"
        : "+f"(c[0]), "+f"(c[1]), "+f"(c[2]), "+f"(c[3])
        : "r"(a[0]), "r"(a[1]), "r"(a[2]), "r"(a[3]), "r"(b[0]), "r"(b[1]));
}
__device__ __forceinline__ void ldmx4(uint32_t* r, uint32_t addr) {
    asm volatile("ldmatrix.sync.aligned.m8n8.x4.shared.b16 {%0,%1,%2,%3}, [%4];"
                 : "=r"(r[0]), "=r"(r[1]), "=r"(r[2]), "=r"(r[3]) : "r"(addr));
}
__device__ __forceinline__ void ldmx4t(uint32_t* r, uint32_t addr) {
    asm volatile("ldmatrix.sync.aligned.m8n8.x4.trans.shared.b16 {%0,%1,%2,%3}, [%4];"
                 : "=r"(r[0]), "=r"(r[1]), "=r"(r[2]), "=r"(r[3]) : "r"(addr));
}
__device__ __forceinline__ void cp16(uint32_t s, const void* g) {
    asm volatile("cp.async.cg.shared.global [%0], [%1], 16;" :: "r"(s), "l"(g));
}
#define CP_COMMIT asm volatile("cp.async.commit_group;")
#define CP_WAIT0  asm volatile("cp.async.wait_group 0;")

__device__ __forceinline__ uint32_t pack_bf16(float lo, float hi) {
    uint32_t d;
    asm("cvt.rn.bf16x2.f32 %0, %1, %2;" : "=r"(d) : "f"(hi), "f"(lo));
    return d;
}
// v0 -> low half (even col), v1 -> high half; hi = bf16 pair, lo = residual pair
__device__ __forceinline__ void split2(float v0, float v1,
                                       uint32_t& hi, uint32_t& lo) {
    uint32_t h = pack_bf16(v0, v1);
    __nv_bfloat162 hb = *(__nv_bfloat162*)&h;
    float r0 = v0 - __bfloat162float(hb.x);
    float r1 = v1 - __bfloat162float(hb.y);
    hi = h;
    lo = pack_bf16(r0, r1);
}

// ---------------------------------------------------------------------------
// Split x into bf16 hi/lo.
// ---------------------------------------------------------------------------
__global__ __launch_bounds__(256) void split_x_kernel(const float* __restrict__ x)
{
    int f = blockIdx.x * 256 + threadIdx.x;
    float4 v = ((const float4*)x)[f];
    uint32_t h0, l0, h1, l1;
    split2(v.x, v.y, h0, l0);
    split2(v.z, v.w, h1, l1);
    ((uint32_t*)g_xhi)[2 * f]     = h0;
    ((uint32_t*)g_xhi)[2 * f + 1] = h1;
    ((uint32_t*)g_xlo)[2 * f]     = l0;
    ((uint32_t*)g_xlo)[2 * f + 1] = l1;
}

// ---------------------------------------------------------------------------
// Transpose + split W: g_w{hi,lo}[z][n][k] = split(W_z[k][n]).
// ---------------------------------------------------------------------------
__global__ __launch_bounds__(256) void transpose_split_w_kernel(
    const float* __restrict__ Wq, const float* __restrict__ Wk,
    const float* __restrict__ Wv)
{
    __shared__ float tile[32][33];
    const float* W = (blockIdx.z == 0) ? Wq : (blockIdx.z == 1) ? Wk : Wv;
    const int tx = threadIdx.x, ty = threadIdx.y;
    const int k0 = blockIdx.y * 32, n0 = blockIdx.x * 32;
#pragma unroll
    for (int i = 0; i < 4; i++)
        tile[ty + 8 * i][tx] = W[(size_t)(k0 + ty + 8 * i) * EMBED + n0 + tx];
    __syncthreads();
    size_t zb = (size_t)blockIdx.z * EMBED * EMBED;
#pragma unroll
    for (int i = 0; i < 4; i++) {
        float v = tile[tx][ty + 8 * i];
        __nv_bfloat16 h = __float2bfloat16(v);
        __nv_bfloat16 l = __float2bfloat16(v - __bfloat162float(h));
        size_t o = zb + (size_t)(n0 + ty + 8 * i) * EMBED + k0 + tx;
        g_whi[o] = h;
        g_wlo[o] = l;
    }
}

// ---------------------------------------------------------------------------
// QKV GEMM with mma.sync bf16 3-way split.
// CTA: 128(M) x 128(N), 8 warps in 2x4, warp tile 64x32. K chunks of 64.
// smem per chunk: Ahi/Alo/Bhi/Blo [128][72] bf16 = 73728 B (single buffer).
// Output: bf16 hi/lo of q/k/v in [B*H][S][64].
// ---------------------------------------------------------------------------
#define AST 72
#define ARR (128 * AST)            // elems per array
#define QKV_SMEM (4 * ARR * 2)     // bytes

__global__ __launch_bounds__(256) void qkv_mma_kernel(
    const float* __restrict__ bq, const float* __restrict__ bk,
    const float* __restrict__ bv)
{
    extern __shared__ __nv_bfloat16 smem[];
    const uint32_t sb = smem_u32(smem);
    const int t = threadIdx.x;
    const int wid = t >> 5;
    const int l = t & 31;
    const int warp_m = wid >> 2;     // 0..1
    const int warp_n = wid & 3;      // 0..3
    const int z = blockIdx.z;
    const int m0 = blockIdx.y * 128;
    const int n0 = blockIdx.x * 128;

    const float* bias = (z == 0) ? bq : (z == 1) ? bk : bv;
    __nv_bfloat16* ohi = (z == 0) ? g_qhi : (z == 1) ? g_khi : g_vhi;
    __nv_bfloat16* olo = (z == 0) ? g_qlo : (z == 1) ? g_klo : g_vlo;
    const __nv_bfloat16* whi = g_whi + (size_t)z * EMBED * EMBED;
    const __nv_bfloat16* wlo = g_wlo + (size_t)z * EMBED * EMBED;

    // lane-dependent ldmatrix offsets (bytes)
    const uint32_t a_row = (l & 15);
    const uint32_t a_col = (l & 16) ? 8 : 0;
    const uint32_t b_nr  = (l & 7) + ((l & 16) ? 8 : 0);
    const uint32_t b_kc  = (l & 8) ? 8 : 0;

    float acc[4][4][4] = {};   // [mf][nt][reg]

    for (int c = 0; c < 16; c++) {
        const int k0 = c * 64;
        __syncthreads();
        // load chunk: 4 arrays x 128 rows x 64 bf16
#pragma unroll
        for (int p = 0; p < 16; p++) {
            int f = p * 256 + t;
            int arr = f >> 10;
            int rem = f & 1023;
            int r = rem >> 3;
            int u = rem & 7;
            uint32_t dst = sb + (uint32_t)(arr * ARR + r * AST + u * 8) * 2;
            const __nv_bfloat16* src;
            if (arr == 0)      src = g_xhi + (size_t)(m0 + r) * EMBED + k0 + u * 8;
            else if (arr == 1) src = g_xlo + (size_t)(m0 + r) * EMBED + k0 + u * 8;
            else if (arr == 2) src = whi   + (size_t)(n0 + r) * EMBED + k0 + u * 8;
            else               src = wlo   + (size_t)(n0 + r) * EMBED + k0 + u * 8;
            cp16(dst, src);
        }
        CP_COMMIT;
        CP_WAIT0;
        __syncthreads();

#pragma unroll
        for (int ks = 0; ks < 4; ks++) {
            uint32_t ah[2][4], al[2][4];
#pragma unroll
            for (int mf = 0; mf < 4; mf++) {
                uint32_t ao = sb + (uint32_t)((warp_m * 64 + mf * 16 + a_row) * AST
                                              + ks * 16 + a_col) * 2;
                uint32_t* dst = (mf & 1) ? ah[1] : ah[0];
                // load hi and lo A frags for this mf
                uint32_t tmp_h[4], tmp_l[4];
                ldmx4(tmp_h, ao);
                ldmx4(tmp_l, ao + ARR * 2);
                // compute B frags lazily below; store A frags in local arrays
                // (use per-mf immediately to limit registers)
#pragma unroll
                for (int bg = 0; bg < 2; bg++) {
                    uint32_t bo = sb + (uint32_t)(2 * ARR + (warp_n * 32 + bg * 16 + b_nr) * AST
                                                  + ks * 16 + b_kc) * 2;
                    uint32_t bh_[4], bl_[4];
                    ldmx4(bh_, bo);
                    ldmx4(bl_, bo + ARR * 2);
                    mma16816(acc[mf][2 * bg],     tmp_h, &bh_[0]);
                    mma16816(acc[mf][2 * bg],     tmp_h, &bl_[0]);
                    mma16816(acc[mf][2 * bg],     tmp_l, &bh_[0]);
                    mma16816(acc[mf][2 * bg + 1], tmp_h, &bh_[2]);
                    mma16816(acc[mf][2 * bg + 1], tmp_h, &bl_[2]);
                    mma16816(acc[mf][2 * bg + 1], tmp_l, &bh_[2]);
                }
                (void)dst; (void)al;
            }
        }
    }

    // epilogue: add bias, split to bf16 hi/lo, write [B*H][S][64]
#pragma unroll
    for (int mf = 0; mf < 4; mf++) {
        int row0 = m0 + warp_m * 64 + mf * 16 + (l >> 2);
#pragma unroll
        for (int nt = 0; nt < 4; nt++) {
            int col = n0 + warp_n * 32 + nt * 8 + (l & 3) * 2;
            float b0 = bias[col], b1 = bias[col + 1];
            int h = col >> 6;
            int hc = col & 63;
#pragma unroll
            for (int rr = 0; rr < 2; rr++) {
                int row = row0 + rr * 8;
                int b = row >> 11;
                int s = row & (SEQ - 1);
                float v0 = acc[mf][nt][2 * rr]     + b0;
                float v1 = acc[mf][nt][2 * rr + 1] + b1;
                uint32_t hi, lo;
                split2(v0, v1, hi, lo);
                size_t idx = (((size_t)(b * NHEAD + h)) * SEQ + s) * HD + hc;
                *(uint32_t*)&ohi[idx] = hi;
                *(uint32_t*)&olo[idx] = lo;
            }
        }
    }
}

// ---------------------------------------------------------------------------
// Flash attention with mma.sync bf16 3-way split.
// CTA: 128 q rows, 8 warps (16 q rows each), BK=128 keys per tile.
// Q/K in natural [row][d] smem; K frags non-trans, V frags via ldmatrix.trans.
// S in C-fragments -> row softmax via 2 quad shuffles -> P packed to bf16
// A-fragments in registers (no smem round trip).
// smem: Qhi/Qlo + Khi/Klo/Vhi/Vlo, each [128][72] bf16 -> 110592 B.
// ---------------------------------------------------------------------------
#define ATT_Q 0
#define ATT_K (2 * ARR)
#define ATT_SMEM (6 * ARR * 2)

__global__ __launch_bounds__(256) void attn_mma_kernel(float* __restrict__ out)
{
    extern __shared__ __nv_bfloat16 smem[];
    const uint32_t sb = smem_u32(smem);
    const int t = threadIdx.x;
    const int w = t >> 5;
    const int l = t & 31;
    const int bh = blockIdx.y;
    const int q0 = blockIdx.x * 128;

    const __nv_bfloat16* qh = g_qhi + (size_t)bh * SEQ * HD;
    const __nv_bfloat16* ql = g_qlo + (size_t)bh * SEQ * HD;
    const __nv_bfloat16* kh = g_khi + (size_t)bh * SEQ * HD;
    const __nv_bfloat16* kl = g_klo + (size_t)bh * SEQ * HD;
    const __nv_bfloat16* vh = g_vhi + (size_t)bh * SEQ * HD;
    const __nv_bfloat16* vl = g_vlo + (size_t)bh * SEQ * HD;

    // lane-dependent ldmatrix offsets
    const uint32_t a_row = (l & 15);
    const uint32_t a_col = (l & 16) ? 8 : 0;
    const uint32_t k_nr  = (l & 7) + ((l & 16) ? 8 : 0);
    const uint32_t k_kc  = (l & 8) ? 8 : 0;
    const uint32_t v_cr  = (l & 7) + ((l & 8) ? 8 : 0);
    const uint32_t v_dc  = (l & 16) ? 8 : 0;

    // ---- load Q tile into smem, then into A-fragment registers ----
#pragma unroll
    for (int p = 0; p < 8; p++) {
        int f = p * 256 + t;
        int arr = f >> 10;          // 0 = hi, 1 = lo
        int rem = f & 1023;
        int r = rem >> 3;
        int u = rem & 7;
        uint32_t dst = sb + (uint32_t)(arr * ARR + r * AST + u * 8) * 2;
        const __nv_bfloat16* src = (arr ? ql : qh) + (size_t)(q0 + r) * HD + u * 8;
        cp16(dst, src);
    }
    CP_COMMIT;
    CP_WAIT0;
    __syncthreads();

    uint32_t qfh[4][4], qfl[4][4];
#pragma unroll
    for (int d16 = 0; d16 < 4; d16++) {
        uint32_t ao = sb + (uint32_t)((w * 16 + a_row) * AST + d16 * 16 + a_col) * 2;
        ldmx4(qfh[d16], ao);
        ldmx4(qfl[d16], ao + ARR * 2);
    }

    float m0r = -1e30f, m1r = -1e30f, l0r = 0.f, l1r = 0.f;
    float o[8][4] = {};

    for (int kt = 0; kt < SEQ; kt += 128) {
        __syncthreads();
        // ---- load K/V tiles (hi/lo) ----
#pragma unroll
        for (int p = 0; p < 16; p++) {
            int f = p * 256 + t;
            int arr = f >> 10;      // 0 khi, 1 klo, 2 vhi, 3 vlo
            int rem = f & 1023;
            int r = rem >> 3;
            int u = rem & 7;
            uint32_t dst = sb + (uint32_t)(ATT_K + arr * ARR + r * AST + u * 8) * 2;
            const __nv_bfloat16* src;
            if (arr == 0)      src = kh + (size_t)(kt + r) * HD + u * 8;
            else if (arr == 1) src = kl + (size_t)(kt + r) * HD + u * 8;
            else if (arr == 2) src = vh + (size_t)(kt + r) * HD + u * 8;
            else               src = vl + (size_t)(kt + r) * HD + u * 8;
            cp16(dst, src);
        }
        CP_COMMIT;
        CP_WAIT0;
        __syncthreads();

        // ---- S = Q K^T ----
        float s[16][4] = {};
#pragma unroll
        for (int d16 = 0; d16 < 4; d16++) {
#pragma unroll
            for (int bg = 0; bg < 8; bg++) {
                uint32_t ko = sb + (uint32_t)(ATT_K + (bg * 16 + k_nr) * AST
                                              + d16 * 16 + k_kc) * 2;
                uint32_t kfh[4], kfl[4];
                ldmx4(kfh, ko);
                ldmx4(kfl, ko + ARR * 2);
                mma16816(s[2 * bg],     qfh[d16], &kfh[0]);
                mma16816(s[2 * bg],     qfh[d16], &kfl[0]);
                mma16816(s[2 * bg],     qfl[d16], &kfh[0]);
                mma16816(s[2 * bg + 1], qfh[d16], &kfh[2]);
                mma16816(s[2 * bg + 1], qfh[d16], &kfl[2]);
                mma16816(s[2 * bg + 1], qfl[d16], &kfh[2]);
            }
        }

        // ---- online softmax (rows l/4 and l/4+8) ----
        float tm0 = -1e30f, tm1 = -1e30f;
#pragma unroll
        for (int nf = 0; nf < 16; nf++) {
            tm0 = fmaxf(tm0, fmaxf(s[nf][0], s[nf][1]));
            tm1 = fmaxf(tm1, fmaxf(s[nf][2], s[nf][3]));
        }
#pragma unroll
        for (int msk = 1; msk < 4; msk <<= 1) {
            tm0 = fmaxf(tm0, __shfl_xor_sync(0xffffffffu, tm0, msk));
            tm1 = fmaxf(tm1, __shfl_xor_sync(0xffffffffu, tm1, msk));
        }
        float mn0 = fmaxf(m0r, tm0), mn1 = fmaxf(m1r, tm1);
        float c0 = __expf(m0r - mn0), c1 = __expf(m1r - mn1);
        m0r = mn0; m1r = mn1;
        float rs0 = 0.f, rs1 = 0.f;
#pragma unroll
        for (int nf = 0; nf < 16; nf++) {
            s[nf][0] = __expf(s[nf][0] - mn0); rs0 += s[nf][0];
            s[nf][1] = __expf(s[nf][1] - mn0); rs0 += s[nf][1];
            s[nf][2] = __expf(s[nf][2] - mn1); rs1 += s[nf][2];
            s[nf][3] = __expf(s[nf][3] - mn1); rs1 += s[nf][3];
        }
#pragma unroll
        for (int msk = 1; msk < 4; msk <<= 1) {
            rs0 += __shfl_xor_sync(0xffffffffu, rs0, msk);
            rs1 += __shfl_xor_sync(0xffffffffu, rs1, msk);
        }
        l0r = l0r * c0 + rs0;
        l1r = l1r * c1 + rs1;
#pragma unroll
        for (int nf = 0; nf < 8; nf++) {
            o[nf][0] *= c0; o[nf][1] *= c0;
            o[nf][2] *= c1; o[nf][3] *= c1;
        }

        // ---- pack P into bf16 A-fragments (hi/lo) ----
        uint32_t pfh[8][4], pfl[8][4];
#pragma unroll
        for (int kt16 = 0; kt16 < 8; kt16++) {
            split2(s[2 * kt16][0],     s[2 * kt16][1],     pfh[kt16][0], pfl[kt16][0]);
            split2(s[2 * kt16][2],     s[2 * kt16][3],     pfh[kt16][1], pfl[kt16][1]);
            split2(s[2 * kt16 + 1][0], s[2 * kt16 + 1][1], pfh[kt16][2], pfl[kt16][2]);
            split2(s[2 * kt16 + 1][2], s[2 * kt16 + 1][3], pfh[kt16][3], pfl[kt16][3]);
        }

        // ---- O += P V ----
#pragma unroll
        for (int dg = 0; dg < 4; dg++) {
#pragma unroll
            for (int kt16 = 0; kt16 < 8; kt16++) {
                uint32_t vo = sb + (uint32_t)(ATT_K + 2 * ARR + (kt16 * 16 + v_cr) * AST
                                              + dg * 16 + v_dc) * 2;
                uint32_t vfh[4], vfl[4];
                ldmx4t(vfh, vo);
                ldmx4t(vfl, vo + ARR * 2);
                mma16816(o[2 * dg],     pfh[kt16], &vfh[0]);
                mma16816(o[2 * dg],     pfh[kt16], &vfl[0]);
                mma16816(o[2 * dg],     pfl[kt16], &vfh[0]);
                mma16816(o[2 * dg + 1], pfh[kt16], &vfh[2]);
                mma16816(o[2 * dg + 1], pfh[kt16], &vfl[2]);
                mma16816(o[2 * dg + 1], pfl[kt16], &vfh[2]);
            }
        }
    }

    // ---- normalize, write out [B][S][1024] ----
    const int b = bh >> 4;
    const int h = bh & 15;
    float inv0 = 1.0f / l0r, inv1 = 1.0f / l1r;
    int row0 = q0 + w * 16 + (l >> 2);
#pragma unroll
    for (int nt = 0; nt < 8; nt++) {
        int col = h * 64 + nt * 8 + (l & 3) * 2;
        size_t i0 = ((size_t)b * SEQ + row0) * EMBED + col;
        size_t i1 = ((size_t)b * SEQ + row0 + 8) * EMBED + col;
        *(float2*)&out[i0] = make_float2(o[nt][0] * inv0, o[nt][1] * inv0);
        *(float2*)&out[i1] = make_float2(o[nt][2] * inv1, o[nt][3] * inv1);
    }
}

// ---------------------------------------------------------------------------
extern "C" void kernel_launch(void* const* d_in, const int* in_sizes, int n_in,
                              void* d_out, int out_size)
{
    const float* x  = (const float*)d_in[0];
    const float* Wq = (const float*)d_in[1];
    const float* bq = (const float*)d_in[2];
    const float* Wk = (const float*)d_in[3];
    const float* bk = (const float*)d_in[4];
    const float* Wv = (const float*)d_in[5];
    const float* bv = (const float*)d_in[6];
    float* out = (float*)d_out;

    split_x_kernel<<<ROWS * EMBED / 4 / 256, 256>>>(x);
    dim3 gt(EMBED / 32, EMBED / 32, 3);
    transpose_split_w_kernel<<<gt, dim3(32, 8)>>>(Wq, Wk, Wv);

    cudaFuncSetAttribute(qkv_mma_kernel,
                         cudaFuncAttributeMaxDynamicSharedMemorySize, QKV_SMEM);
    dim3 gq(EMBED / 128, ROWS / 128, 3);
    qkv_mma_kernel<<<gq, 256, QKV_SMEM>>>(bq, bk, bv);

    cudaFuncSetAttribute(attn_mma_kernel,
                         cudaFuncAttributeMaxDynamicSharedMemorySize, ATT_SMEM);
    dim3 g2(SEQ / 128, BATCH * NHEAD);
    attn_mma_kernel<<<g2, 256, ATT_SMEM>>>(out);
}

// round 5
// speedup vs baseline: 2.9451x; 1.0819x over previous
#include <cuda_runtime.h>
#include <cuda_bf16.h>
#include <cstdint>

#define EMBED 1024
#define NHEAD 16
#define HD 64
#define BATCH 2
#define SEQ 2048
#define ROWS (BATCH * SEQ)   // 4096

// bf16 hi/lo split of x [4096][1024] and of W^T [3][1024(n)][1024(k)].
__device__ __nv_bfloat16 g_xhi[(size_t)ROWS * EMBED];
__device__ __nv_bfloat16 g_xlo[(size_t)ROWS * EMBED];
__device__ __nv_bfloat16 g_whi[(size_t)3 * EMBED * EMBED];
__device__ __nv_bfloat16 g_wlo[(size_t)3 * EMBED * EMBED];

// bf16 hi/lo Q/K/V in [B*H][S][64] layout.
__device__ __nv_bfloat16 g_qhi[(size_t)ROWS * NHEAD * HD];
__device__ __nv_bfloat16 g_qlo[(size_t)ROWS * NHEAD * HD];
__device__ __nv_bfloat16 g_khi[(size_t)ROWS * NHEAD * HD];
__device__ __nv_bfloat16 g_klo[(size_t)ROWS * NHEAD * HD];
__device__ __nv_bfloat16 g_vhi[(size_t)ROWS * NHEAD * HD];
__device__ __nv_bfloat16 g_vlo[(size_t)ROWS * NHEAD * HD];

// ---------------------------------------------------------------------------
// helpers
// ---------------------------------------------------------------------------
__device__ __forceinline__ uint32_t smem_u32(const void* p) {
    uint32_t a;
    asm("{ .reg .u64 t; cvta.to.shared.u64 t, %1; cvt.u32.u64 %0, t; }"
        : "=r"(a) : "l"(p));
    return a;
}
__device__ __forceinline__ void mma16816(float* c, const uint32_t* a,
                                         const uint32_t* b) {
    asm volatile(
        "mma.sync.aligned.m16n8k16.row.col.f32.bf16.bf16.f32 "
        "{%0,%1,%2,%3}, {%4,%5,%6,%7}, {%8,%9}, {%0,%1,%2,%3};"
        : "+f"(c[0]), "+f"(c[1]), "+f"(c[2]), "+f"(c[3])
        : "r"(a[0]), "r"(a[1]), "r"(a[2]), "r"(a[3]), "r"(b[0]), "r"(b[1]));
}
__device__ __forceinline__ void ldmx4(uint32_t* r, uint32_t addr) {
    asm volatile("ldmatrix.sync.aligned.m8n8.x4.shared.b16 {%0,%1,%2,%3}, [%4];"
                 : "=r"(r[0]), "=r"(r[1]), "=r"(r[2]), "=r"(r[3]) : "r"(addr));
}
__device__ __forceinline__ void ldmx4t(uint32_t* r, uint32_t addr) {
    asm volatile("ldmatrix.sync.aligned.m8n8.x4.trans.shared.b16 {%0,%1,%2,%3}, [%4];"
                 : "=r"(r[0]), "=r"(r[1]), "=r"(r[2]), "=r"(r[3]) : "r"(addr));
}
__device__ __forceinline__ void cp16(uint32_t s, const void* g) {
    asm volatile("cp.async.cg.shared.global [%0], [%1], 16;" :: "r"(s), "l"(g));
}
#define CP_COMMIT asm volatile("cp.async.commit_group;")
#define CP_WAIT0  asm volatile("cp.async.wait_group 0;")
#define CP_WAIT1  asm volatile("cp.async.wait_group 1;")

__device__ __forceinline__ uint32_t pack_bf16(float lo, float hi) {
    uint32_t d;
    asm("cvt.rn.bf16x2.f32 %0, %1, %2;" : "=r"(d) : "f"(hi), "f"(lo));
    return d;
}
__device__ __forceinline__ void split2(float v0, float v1,
                                       uint32_t& hi, uint32_t& lo) {
    uint32_t h = pack_bf16(v0, v1);
    __nv_bfloat162 hb = *(__nv_bfloat162*)&h;
    float r0 = v0 - __bfloat162float(hb.x);
    float r1 = v1 - __bfloat162float(hb.y);
    hi = h;
    lo = pack_bf16(r0, r1);
}

// ---------------------------------------------------------------------------
// Split x into bf16 hi/lo.
// ---------------------------------------------------------------------------
__global__ __launch_bounds__(256) void split_x_kernel(const float* __restrict__ x)
{
    int f = blockIdx.x * 256 + threadIdx.x;
    float4 v = ((const float4*)x)[f];
    uint32_t h0, l0, h1, l1;
    split2(v.x, v.y, h0, l0);
    split2(v.z, v.w, h1, l1);
    ((uint32_t*)g_xhi)[2 * f]     = h0;
    ((uint32_t*)g_xhi)[2 * f + 1] = h1;
    ((uint32_t*)g_xlo)[2 * f]     = l0;
    ((uint32_t*)g_xlo)[2 * f + 1] = l1;
}

// ---------------------------------------------------------------------------
// Transpose + split W: g_w{hi,lo}[z][n][k] = split(W_z[k][n]).
// ---------------------------------------------------------------------------
__global__ __launch_bounds__(256) void transpose_split_w_kernel(
    const float* __restrict__ Wq, const float* __restrict__ Wk,
    const float* __restrict__ Wv)
{
    __shared__ float tile[32][33];
    const float* W = (blockIdx.z == 0) ? Wq : (blockIdx.z == 1) ? Wk : Wv;
    const int tx = threadIdx.x, ty = threadIdx.y;
    const int k0 = blockIdx.y * 32, n0 = blockIdx.x * 32;
#pragma unroll
    for (int i = 0; i < 4; i++)
        tile[ty + 8 * i][tx] = W[(size_t)(k0 + ty + 8 * i) * EMBED + n0 + tx];
    __syncthreads();
    size_t zb = (size_t)blockIdx.z * EMBED * EMBED;
#pragma unroll
    for (int i = 0; i < 4; i++) {
        float v = tile[tx][ty + 8 * i];
        __nv_bfloat16 h = __float2bfloat16(v);
        __nv_bfloat16 l = __float2bfloat16(v - __bfloat162float(h));
        size_t o = zb + (size_t)(n0 + ty + 8 * i) * EMBED + k0 + tx;
        g_whi[o] = h;
        g_wlo[o] = l;
    }
}

// ---------------------------------------------------------------------------
// QKV GEMM with mma.sync bf16 3-way split, double-buffered cp.async.
// CTA: 128(M) x 128(N), 8 warps in 2x4, warp tile 64x32. K chunks of 64.
// smem: 2 stages x {Ahi,Alo,Bhi,Blo}[128][72] bf16 = 147456 B.
// ---------------------------------------------------------------------------
#define AST 72
#define ARR (128 * AST)            // elems per array
#define STG (4 * ARR)              // elems per stage
#define QKV_SMEM (2 * STG * 2)     // bytes

__global__ __launch_bounds__(256) void qkv_mma_kernel(
    const float* __restrict__ bq, const float* __restrict__ bk,
    const float* __restrict__ bv)
{
    extern __shared__ __nv_bfloat16 smem[];
    const uint32_t sb = smem_u32(smem);
    const int t = threadIdx.x;
    const int wid = t >> 5;
    const int l = t & 31;
    const int warp_m = wid >> 2;     // 0..1
    const int warp_n = wid & 3;      // 0..3
    const int z = blockIdx.z;
    const int m0 = blockIdx.y * 128;
    const int n0 = blockIdx.x * 128;

    const float* bias = (z == 0) ? bq : (z == 1) ? bk : bv;
    __nv_bfloat16* ohi = (z == 0) ? g_qhi : (z == 1) ? g_khi : g_vhi;
    __nv_bfloat16* olo = (z == 0) ? g_qlo : (z == 1) ? g_klo : g_vlo;
    const __nv_bfloat16* whi = g_whi + (size_t)z * EMBED * EMBED;
    const __nv_bfloat16* wlo = g_wlo + (size_t)z * EMBED * EMBED;

    const uint32_t a_row = (l & 15);
    const uint32_t a_col = (l & 16) ? 8 : 0;
    const uint32_t b_nr  = (l & 7) + ((l & 16) ? 8 : 0);
    const uint32_t b_kc  = (l & 8) ? 8 : 0;

    float acc[4][4][4] = {};   // [mf][nt][reg]

    auto issue_chunk = [&](int c, int stg) {
        const int k0 = c * 64;
        const uint32_t base = (uint32_t)stg * STG;
#pragma unroll
        for (int p = 0; p < 16; p++) {
            int f = p * 256 + t;
            int arr = f >> 10;
            int rem = f & 1023;
            int r = rem >> 3;
            int u = rem & 7;
            uint32_t dst = sb + (uint32_t)(base + arr * ARR + r * AST + u * 8) * 2;
            const __nv_bfloat16* src;
            if (arr == 0)      src = g_xhi + (size_t)(m0 + r) * EMBED + k0 + u * 8;
            else if (arr == 1) src = g_xlo + (size_t)(m0 + r) * EMBED + k0 + u * 8;
            else if (arr == 2) src = whi   + (size_t)(n0 + r) * EMBED + k0 + u * 8;
            else               src = wlo   + (size_t)(n0 + r) * EMBED + k0 + u * 8;
            cp16(dst, src);
        }
        CP_COMMIT;
    };

    issue_chunk(0, 0);

    for (int c = 0; c < 16; c++) {
        if (c < 15) issue_chunk(c + 1, (c + 1) & 1);
        if (c < 15) { CP_WAIT1; } else { CP_WAIT0; }
        __syncthreads();

        const uint32_t base = (uint32_t)(c & 1) * STG;
#pragma unroll
        for (int ks = 0; ks < 4; ks++) {
#pragma unroll
            for (int mf = 0; mf < 4; mf++) {
                uint32_t ao = sb + (uint32_t)(base + (warp_m * 64 + mf * 16 + a_row) * AST
                                              + ks * 16 + a_col) * 2;
                uint32_t tmp_h[4], tmp_l[4];
                ldmx4(tmp_h, ao);
                ldmx4(tmp_l, ao + ARR * 2);
#pragma unroll
                for (int bg = 0; bg < 2; bg++) {
                    uint32_t bo = sb + (uint32_t)(base + 2 * ARR
                                                  + (warp_n * 32 + bg * 16 + b_nr) * AST
                                                  + ks * 16 + b_kc) * 2;
                    uint32_t bh_[4], bl_[4];
                    ldmx4(bh_, bo);
                    ldmx4(bl_, bo + ARR * 2);
                    mma16816(acc[mf][2 * bg],     tmp_h, &bh_[0]);
                    mma16816(acc[mf][2 * bg],     tmp_h, &bl_[0]);
                    mma16816(acc[mf][2 * bg],     tmp_l, &bh_[0]);
                    mma16816(acc[mf][2 * bg + 1], tmp_h, &bh_[2]);
                    mma16816(acc[mf][2 * bg + 1], tmp_h, &bl_[2]);
                    mma16816(acc[mf][2 * bg + 1], tmp_l, &bh_[2]);
                }
            }
        }
        __syncthreads();
    }

    // epilogue: add bias, split to bf16 hi/lo, write [B*H][S][64]
#pragma unroll
    for (int mf = 0; mf < 4; mf++) {
        int row0 = m0 + warp_m * 64 + mf * 16 + (l >> 2);
#pragma unroll
        for (int nt = 0; nt < 4; nt++) {
            int col = n0 + warp_n * 32 + nt * 8 + (l & 3) * 2;
            float b0 = bias[col], b1 = bias[col + 1];
            int h = col >> 6;
            int hc = col & 63;
#pragma unroll
            for (int rr = 0; rr < 2; rr++) {
                int row = row0 + rr * 8;
                int b = row >> 11;
                int s = row & (SEQ - 1);
                float v0 = acc[mf][nt][2 * rr]     + b0;
                float v1 = acc[mf][nt][2 * rr + 1] + b1;
                uint32_t hi, lo;
                split2(v0, v1, hi, lo);
                size_t idx = (((size_t)(b * NHEAD + h)) * SEQ + s) * HD + hc;
                *(uint32_t*)&ohi[idx] = hi;
                *(uint32_t*)&olo[idx] = lo;
            }
        }
    }
}

// ---------------------------------------------------------------------------
// Flash attention with mma.sync bf16 3-way split, double-buffered K/V.
// CTA: 128 q rows, 8 warps (16 q rows each), BK=128 keys per tile.
// smem: 2 stages x {Khi,Klo,Vhi,Vlo}[128][72] = 147456 B; Q aliased in stage 1.
// ---------------------------------------------------------------------------
#define ATT_SMEM (2 * STG * 2)

__global__ __launch_bounds__(256) void attn_mma_kernel(float* __restrict__ out)
{
    extern __shared__ __nv_bfloat16 smem[];
    const uint32_t sb = smem_u32(smem);
    const int t = threadIdx.x;
    const int w = t >> 5;
    const int l = t & 31;
    const int bh = blockIdx.y;
    const int q0 = blockIdx.x * 128;

    const __nv_bfloat16* qh = g_qhi + (size_t)bh * SEQ * HD;
    const __nv_bfloat16* ql = g_qlo + (size_t)bh * SEQ * HD;
    const __nv_bfloat16* kh = g_khi + (size_t)bh * SEQ * HD;
    const __nv_bfloat16* kl = g_klo + (size_t)bh * SEQ * HD;
    const __nv_bfloat16* vh = g_vhi + (size_t)bh * SEQ * HD;
    const __nv_bfloat16* vl = g_vlo + (size_t)bh * SEQ * HD;

    const uint32_t a_row = (l & 15);
    const uint32_t a_col = (l & 16) ? 8 : 0;
    const uint32_t k_nr  = (l & 7) + ((l & 16) ? 8 : 0);
    const uint32_t k_kc  = (l & 8) ? 8 : 0;
    const uint32_t v_cr  = (l & 7) + ((l & 8) ? 8 : 0);
    const uint32_t v_dc  = (l & 16) ? 8 : 0;

    auto issue_kv = [&](int kt, int stg) {
        const uint32_t base = (uint32_t)stg * STG;
#pragma unroll
        for (int p = 0; p < 16; p++) {
            int f = p * 256 + t;
            int arr = f >> 10;      // 0 khi, 1 klo, 2 vhi, 3 vlo
            int rem = f & 1023;
            int r = rem >> 3;
            int u = rem & 7;
            uint32_t dst = sb + (uint32_t)(base + arr * ARR + r * AST + u * 8) * 2;
            const __nv_bfloat16* src;
            if (arr == 0)      src = kh + (size_t)(kt + r) * HD + u * 8;
            else if (arr == 1) src = kl + (size_t)(kt + r) * HD + u * 8;
            else if (arr == 2) src = vh + (size_t)(kt + r) * HD + u * 8;
            else               src = vl + (size_t)(kt + r) * HD + u * 8;
            cp16(dst, src);
        }
        CP_COMMIT;
    };

    // ---- load Q into stage-1 space (consumed into regs before tile 1 lands)
#pragma unroll
    for (int p = 0; p < 8; p++) {
        int f = p * 256 + t;
        int arr = f >> 10;          // 0 = hi, 1 = lo
        int rem = f & 1023;
        int r = rem >> 3;
        int u = rem & 7;
        uint32_t dst = sb + (uint32_t)(STG + arr * ARR + r * AST + u * 8) * 2;
        const __nv_bfloat16* src = (arr ? ql : qh) + (size_t)(q0 + r) * HD + u * 8;
        cp16(dst, src);
    }
    CP_COMMIT;
    issue_kv(0, 0);      // tile 0 in flight behind Q
    CP_WAIT1;            // Q arrived
    __syncthreads();

    uint32_t qfh[4][4], qfl[4][4];
#pragma unroll
    for (int d16 = 0; d16 < 4; d16++) {
        uint32_t ao = sb + (uint32_t)(STG + (w * 16 + a_row) * AST + d16 * 16 + a_col) * 2;
        ldmx4(qfh[d16], ao);
        ldmx4(qfl[d16], ao + ARR * 2);
    }
    __syncthreads();     // Q region free for tile-1 overwrite

    float m0r = -1e30f, m1r = -1e30f, l0r = 0.f, l1r = 0.f;
    float o[8][4] = {};

    for (int it = 0; it < 16; it++) {
        if (it < 15) issue_kv((it + 1) * 128, (it + 1) & 1);
        if (it < 15) { CP_WAIT1; } else { CP_WAIT0; }
        __syncthreads();

        const uint32_t base = (uint32_t)(it & 1) * STG;

        // ---- S = Q K^T ----
        float s[16][4] = {};
#pragma unroll
        for (int d16 = 0; d16 < 4; d16++) {
#pragma unroll
            for (int bg = 0; bg < 8; bg++) {
                uint32_t ko = sb + (uint32_t)(base + (bg * 16 + k_nr) * AST
                                              + d16 * 16 + k_kc) * 2;
                uint32_t kfh[4], kfl[4];
                ldmx4(kfh, ko);
                ldmx4(kfl, ko + ARR * 2);
                mma16816(s[2 * bg],     qfh[d16], &kfh[0]);
                mma16816(s[2 * bg],     qfh[d16], &kfl[0]);
                mma16816(s[2 * bg],     qfl[d16], &kfh[0]);
                mma16816(s[2 * bg + 1], qfh[d16], &kfh[2]);
                mma16816(s[2 * bg + 1], qfh[d16], &kfl[2]);
                mma16816(s[2 * bg + 1], qfl[d16], &kfh[2]);
            }
        }

        // ---- online softmax (rows l/4 and l/4+8) ----
        float tm0 = -1e30f, tm1 = -1e30f;
#pragma unroll
        for (int nf = 0; nf < 16; nf++) {
            tm0 = fmaxf(tm0, fmaxf(s[nf][0], s[nf][1]));
            tm1 = fmaxf(tm1, fmaxf(s[nf][2], s[nf][3]));
        }
#pragma unroll
        for (int msk = 1; msk < 4; msk <<= 1) {
            tm0 = fmaxf(tm0, __shfl_xor_sync(0xffffffffu, tm0, msk));
            tm1 = fmaxf(tm1, __shfl_xor_sync(0xffffffffu, tm1, msk));
        }
        float mn0 = fmaxf(m0r, tm0), mn1 = fmaxf(m1r, tm1);
        float c0 = __expf(m0r - mn0), c1 = __expf(m1r - mn1);
        m0r = mn0; m1r = mn1;
        float rs0 = 0.f, rs1 = 0.f;
#pragma unroll
        for (int nf = 0; nf < 16; nf++) {
            s[nf][0] = __expf(s[nf][0] - mn0); rs0 += s[nf][0];
            s[nf][1] = __expf(s[nf][1] - mn0); rs0 += s[nf][1];
            s[nf][2] = __expf(s[nf][2] - mn1); rs1 += s[nf][2];
            s[nf][3] = __expf(s[nf][3] - mn1); rs1 += s[nf][3];
        }
#pragma unroll
        for (int msk = 1; msk < 4; msk <<= 1) {
            rs0 += __shfl_xor_sync(0xffffffffu, rs0, msk);
            rs1 += __shfl_xor_sync(0xffffffffu, rs1, msk);
        }
        l0r = l0r * c0 + rs0;
        l1r = l1r * c1 + rs1;
#pragma unroll
        for (int nf = 0; nf < 8; nf++) {
            o[nf][0] *= c0; o[nf][1] *= c0;
            o[nf][2] *= c1; o[nf][3] *= c1;
        }

        // ---- O += P V, packing P per 16-key group (low register pressure) ----
#pragma unroll
        for (int kt16 = 0; kt16 < 8; kt16++) {
            uint32_t ph[4], pl[4];
            split2(s[2 * kt16][0],     s[2 * kt16][1],     ph[0], pl[0]);
            split2(s[2 * kt16][2],     s[2 * kt16][3],     ph[1], pl[1]);
            split2(s[2 * kt16 + 1][0], s[2 * kt16 + 1][1], ph[2], pl[2]);
            split2(s[2 * kt16 + 1][2], s[2 * kt16 + 1][3], ph[3], pl[3]);
#pragma unroll
            for (int dg = 0; dg < 4; dg++) {
                uint32_t vo = sb + (uint32_t)(base + 2 * ARR + (kt16 * 16 + v_cr) * AST
                                              + dg * 16 + v_dc) * 2;
                uint32_t vfh[4], vfl[4];
                ldmx4t(vfh, vo);
                ldmx4t(vfl, vo + ARR * 2);
                mma16816(o[2 * dg],     ph, &vfh[0]);
                mma16816(o[2 * dg],     ph, &vfl[0]);
                mma16816(o[2 * dg],     pl, &vfh[0]);
                mma16816(o[2 * dg + 1], ph, &vfh[2]);
                mma16816(o[2 * dg + 1], ph, &vfl[2]);
                mma16816(o[2 * dg + 1], pl, &vfh[2]);
            }
        }
        __syncthreads();
    }

    // ---- normalize, write out [B][S][1024] ----
    const int b = bh >> 4;
    const int h = bh & 15;
    float inv0 = 1.0f / l0r, inv1 = 1.0f / l1r;
    int row0 = q0 + w * 16 + (l >> 2);
#pragma unroll
    for (int nt = 0; nt < 8; nt++) {
        int col = h * 64 + nt * 8 + (l & 3) * 2;
        size_t i0 = ((size_t)b * SEQ + row0) * EMBED + col;
        size_t i1 = ((size_t)b * SEQ + row0 + 8) * EMBED + col;
        *(float2*)&out[i0] = make_float2(o[nt][0] * inv0, o[nt][1] * inv0);
        *(float2*)&out[i1] = make_float2(o[nt][2] * inv1, o[nt][3] * inv1);
    }
}

// ---------------------------------------------------------------------------
extern "C" void kernel_launch(void* const* d_in, const int* in_sizes, int n_in,
                              void* d_out, int out_size)
{
    const float* x  = (const float*)d_in[0];
    const float* Wq = (const float*)d_in[1];
    const float* bq = (const float*)d_in[2];
    const float* Wk = (const float*)d_in[3];
    const float* bk = (const float*)d_in[4];
    const float* Wv = (const float*)d_in[5];
    const float* bv = (const float*)d_in[6];
    float* out = (float*)d_out;

    split_x_kernel<<<ROWS * EMBED / 4 / 256, 256>>>(x);
    dim3 gt(EMBED / 32, EMBED / 32, 3);
    transpose_split_w_kernel<<<gt, dim3(32, 8)>>>(Wq, Wk, Wv);

    cudaFuncSetAttribute(qkv_mma_kernel,
                         cudaFuncAttributeMaxDynamicSharedMemorySize, QKV_SMEM);
    dim3 gq(EMBED / 128, ROWS / 128, 3);
    qkv_mma_kernel<<<gq, 256, QKV_SMEM>>>(bq, bk, bv);

    cudaFuncSetAttribute(attn_mma_kernel,
                         cudaFuncAttributeMaxDynamicSharedMemorySize, ATT_SMEM);
    dim3 g2(SEQ / 128, BATCH * NHEAD);
    attn_mma_kernel<<<g2, 256, ATT_SMEM>>>(out);
}